// round 15
// baseline (speedup 1.0000x reference)
#include <cuda_runtime.h>
#include <cstdint>

// ParabolicPool2D: out[b,c,i,j] = max_{p,q in 0..2} f[b,c,2i+p,2j+q] + h[c,p,q]
// h[c,p,q] = -t[c]*(zp^2+zq^2)/2 -> separable with s = t[c]/2:
//   colmax[r][j] = max(f[r][2j]-s, f[r][2j+1], f[r][2j+2]-s)
//   out[i][j]    = max(colmax[2i]-s, colmax[2i+1], colmax[2i+2]-s)
//
// Fine-grained block = one (image, 8-output-row tile), 128 threads,
// 17.5KB smem -> 12 blocks/SM (48 warps, 12 concurrent bulk read streams).
// Reads: TWO cp.async.bulk chunks (9 rows + 8 rows) with separate mbarriers;
//   warp w computes output row w right after chunk A (9.2KB) lands, then row
//   w+4 after chunk B -> exposed load latency per block is halved.
// Writes: direct __stcs scalar stores.

#define Wd 256
#define OWd 127
#define OHd 127

#define NIN_MAX 17

__device__ __forceinline__ uint32_t smem_u32(const void* p) {
    return (uint32_t)__cvta_generic_to_shared(p);
}

__device__ __forceinline__ void mbar_wait(uint32_t mb, uint32_t parity) {
    asm volatile(
        "{\n\t.reg .pred P;\n\t"
        "W_%=:\n\t"
        "mbarrier.try_wait.parity.acquire.cta.shared::cta.b64 P, [%0], %1, 0x989680;\n\t"
        "@P bra.uni D_%=;\n\t"
        "bra.uni W_%=;\n\t"
        "D_%=:\n\t}"
        :: "r"(mb), "r"(parity) : "memory");
}

__device__ __forceinline__ void cm_row(const float* __restrict__ sr, int lane,
                                       float s, float cm[4]) {
    float4 a = *(const float4*)(sr + 4 * lane);
    float4 b = *(const float4*)(sr + 4 * lane + 128);
    float h0 = (lane == 0) ? b.x : a.x;
    int src = (lane + 1) & 31;
    float n0 = __shfl_sync(0xffffffffu, h0, src);   // col 4L+4
    float n1 = __shfl_sync(0xffffffffu, b.x, src);  // col 4L+132 (lane31 unused)
    cm[0] = fmaxf(fmaxf(a.x - s, a.y), a.z - s);    // out col 2L
    cm[1] = fmaxf(fmaxf(a.z - s, a.w), n0 - s);     // out col 2L+1
    cm[2] = fmaxf(fmaxf(b.x - s, b.y), b.z - s);    // out col 2L+64
    cm[3] = fmaxf(fmaxf(b.z - s, b.w), n1 - s);     // out col 2L+65
}

__device__ __forceinline__ void do_row(const float* __restrict__ buf, int i,
                                       float* __restrict__ op, int i0,
                                       int lane, int j0, bool lastlane, float s) {
    const float* r0p = buf + (size_t)(2 * i) * Wd;
    float cmA[4], cmB[4], cmC[4];
    cm_row(r0p,          lane, s, cmA);
    cm_row(r0p + Wd,     lane, s, cmB);
    cm_row(r0p + 2 * Wd, lane, s, cmC);

    float o0 = fmaxf(fmaxf(cmA[0] - s, cmB[0]), cmC[0] - s);
    float o1 = fmaxf(fmaxf(cmA[1] - s, cmB[1]), cmC[1] - s);
    float o2 = fmaxf(fmaxf(cmA[2] - s, cmB[2]), cmC[2] - s);
    float o3 = fmaxf(fmaxf(cmA[3] - s, cmB[3]), cmC[3] - s);

    float* orow = op + (size_t)(i0 + i) * OWd;
    __stcs(orow + j0, o0);
    __stcs(orow + j0 + 1, o1);
    __stcs(orow + j0 + 64, o2);
    if (!lastlane) __stcs(orow + j0 + 65, o3);
}

__global__ void __launch_bounds__(128, 12)
parabolic_pool2d_kernel(const float* __restrict__ f,
                        const float* __restrict__ t,
                        float* __restrict__ out) {
    __shared__ __align__(128) float smi[NIN_MAX * Wd];  // 17 input rows (17408 B)
    __shared__ __align__(8) unsigned long long mbar[2];

    int bid  = blockIdx.x;
    int img  = bid >> 4;                 // image = b*128 + c
    int tile = bid & 15;                 // 8-output-row tile within image
    int i0 = tile << 3;
    int nout = min(8, OHd - i0);         // 8, or 7 for tile 15
    int nin  = 2 * nout + 1;             // 17 or 15 input rows
    int bytesA = 9 * (Wd * 4);           // rows 0..8 (9216 B)
    int bytesB = (nin - 9) * (Wd * 4);   // rows 9..nin-1 (8192 or 6144 B)

    const float* src = f + (size_t)img * (256 * Wd) + (size_t)(i0 << 1) * Wd;

    uint32_t smi_a = smem_u32(smi);
    uint32_t mb0 = smem_u32(&mbar[0]);
    uint32_t mb1 = smem_u32(&mbar[1]);

    if (threadIdx.x == 0) {
        asm volatile("mbarrier.init.shared.b64 [%0], 1;" :: "r"(mb0) : "memory");
        asm volatile("mbarrier.init.shared.b64 [%0], 1;" :: "r"(mb1) : "memory");
    }
    __syncthreads();
    if (threadIdx.x == 0) {
        asm volatile("mbarrier.arrive.expect_tx.shared.b64 _, [%0], %1;"
                     :: "r"(mb0), "r"(bytesA) : "memory");
        asm volatile("cp.async.bulk.shared::cta.global.mbarrier::complete_tx::bytes"
                     " [%0], [%1], %2, [%3];"
                     :: "r"(smi_a), "l"(src), "r"(bytesA), "r"(mb0) : "memory");
        asm volatile("mbarrier.arrive.expect_tx.shared.b64 _, [%0], %1;"
                     :: "r"(mb1), "r"(bytesB) : "memory");
        asm volatile("cp.async.bulk.shared::cta.global.mbarrier::complete_tx::bytes"
                     " [%0], [%1], %2, [%3];"
                     :: "r"(smi_a + 9 * Wd * 4), "l"(src + 9 * Wd),
                        "r"(bytesB), "r"(mb1) : "memory");
    }

    float s = 0.5f * __ldg(t + (img & 127));
    float* op = out + (size_t)img * (OHd * OWd);
    int tid  = threadIdx.x;
    int w    = tid >> 5;                 // 0..3
    int lane = tid & 31;
    int j0   = 2 * lane;
    bool lastlane = (lane == 31);

    // phase 1: output row w (inputs 2w..2w+2 <= 8, chunk A only)
    mbar_wait(mb0, 0);
    do_row(smi, w, op, i0, lane, j0, lastlane, s);

    // phase 2: output row w+4 (inputs 8..16, chunk B)
    mbar_wait(mb1, 0);
    int i = w + 4;
    if (i < nout)
        do_row(smi, i, op, i0, lane, j0, lastlane, s);
}

extern "C" void kernel_launch(void* const* d_in, const int* in_sizes, int n_in,
                              void* d_out, int out_size) {
    const float* f = (const float*)d_in[0];   // [16,128,256,256] fp32
    const float* t = (const float*)d_in[1];   // [128] fp32
    float* out = (float*)d_out;               // [16,128,127,127] fp32
    // 2048 images * 16 tiles = 32768 blocks, 128 threads each
    parabolic_pool2d_kernel<<<32768, 128>>>(f, t, out);
}

// round 16
// speedup vs baseline: 1.0023x; 1.0023x over previous
#include <cuda_runtime.h>
#include <cstdint>

// ParabolicPool2D: out[b,c,i,j] = max_{p,q in 0..2} f[b,c,2i+p,2j+q] + h[c,p,q]
// h[c,p,q] = -t[c]*(zp^2+zq^2)/2 -> separable with s = t[c]/2:
//   colmax[r][j] = max(f[r][2j]-s, f[r][2j+1], f[r][2j+2]-s)
//   out[i][j]    = max(colmax[2i]-s, colmax[2i+1], colmax[2i+2]-s)
//
// Ultra-fine block = one (image, 4-output-row tile), 64 threads, 9.3KB smem
// -> 24 blocks/SM (48 warps, 24 concurrent bulk read streams per SM).
// Reads: TWO cp.async.bulk chunks (5 rows + 4 rows); warp w computes output
//   row w right after chunk A (5KB) lands, then row w+2 after chunk B.
// Writes: direct __stcs scalar stores.

#define Wd 256
#define OWd 127
#define OHd 127

#define NIN_MAX 9

__device__ __forceinline__ uint32_t smem_u32(const void* p) {
    return (uint32_t)__cvta_generic_to_shared(p);
}

__device__ __forceinline__ void mbar_wait(uint32_t mb, uint32_t parity) {
    asm volatile(
        "{\n\t.reg .pred P;\n\t"
        "W_%=:\n\t"
        "mbarrier.try_wait.parity.acquire.cta.shared::cta.b64 P, [%0], %1, 0x989680;\n\t"
        "@P bra.uni D_%=;\n\t"
        "bra.uni W_%=;\n\t"
        "D_%=:\n\t}"
        :: "r"(mb), "r"(parity) : "memory");
}

__device__ __forceinline__ void cm_row(const float* __restrict__ sr, int lane,
                                       float s, float cm[4]) {
    float4 a = *(const float4*)(sr + 4 * lane);
    float4 b = *(const float4*)(sr + 4 * lane + 128);
    float h0 = (lane == 0) ? b.x : a.x;
    int src = (lane + 1) & 31;
    float n0 = __shfl_sync(0xffffffffu, h0, src);   // col 4L+4
    float n1 = __shfl_sync(0xffffffffu, b.x, src);  // col 4L+132 (lane31 unused)
    cm[0] = fmaxf(fmaxf(a.x - s, a.y), a.z - s);    // out col 2L
    cm[1] = fmaxf(fmaxf(a.z - s, a.w), n0 - s);     // out col 2L+1
    cm[2] = fmaxf(fmaxf(b.x - s, b.y), b.z - s);    // out col 2L+64
    cm[3] = fmaxf(fmaxf(b.z - s, b.w), n1 - s);     // out col 2L+65
}

__device__ __forceinline__ void do_row(const float* __restrict__ buf, int i,
                                       float* __restrict__ op, int i0,
                                       int lane, int j0, bool lastlane, float s) {
    const float* r0p = buf + (size_t)(2 * i) * Wd;
    float cmA[4], cmB[4], cmC[4];
    cm_row(r0p,          lane, s, cmA);
    cm_row(r0p + Wd,     lane, s, cmB);
    cm_row(r0p + 2 * Wd, lane, s, cmC);

    float o0 = fmaxf(fmaxf(cmA[0] - s, cmB[0]), cmC[0] - s);
    float o1 = fmaxf(fmaxf(cmA[1] - s, cmB[1]), cmC[1] - s);
    float o2 = fmaxf(fmaxf(cmA[2] - s, cmB[2]), cmC[2] - s);
    float o3 = fmaxf(fmaxf(cmA[3] - s, cmB[3]), cmC[3] - s);

    float* orow = op + (size_t)(i0 + i) * OWd;
    __stcs(orow + j0, o0);
    __stcs(orow + j0 + 1, o1);
    __stcs(orow + j0 + 64, o2);
    if (!lastlane) __stcs(orow + j0 + 65, o3);
}

__global__ void __launch_bounds__(64, 24)
parabolic_pool2d_kernel(const float* __restrict__ f,
                        const float* __restrict__ t,
                        float* __restrict__ out) {
    __shared__ __align__(128) float smi[NIN_MAX * Wd];  // 9 input rows (9216 B)
    __shared__ __align__(8) unsigned long long mbar[2];

    int bid  = blockIdx.x;
    int img  = bid >> 5;                 // image = b*128 + c
    int tile = bid & 31;                 // 4-output-row tile within image
    int i0 = tile << 2;
    int nout = min(4, OHd - i0);         // 4, or 3 for tile 31
    int nin  = 2 * nout + 1;             // 9 or 7 input rows
    int bytesA = 5 * (Wd * 4);           // rows 0..4 (5120 B)
    int bytesB = (nin - 5) * (Wd * 4);   // rows 5..nin-1 (4096 or 2048 B)

    const float* src = f + (size_t)img * (256 * Wd) + (size_t)(i0 << 1) * Wd;

    uint32_t smi_a = smem_u32(smi);
    uint32_t mb0 = smem_u32(&mbar[0]);
    uint32_t mb1 = smem_u32(&mbar[1]);

    if (threadIdx.x == 0) {
        asm volatile("mbarrier.init.shared.b64 [%0], 1;" :: "r"(mb0) : "memory");
        asm volatile("mbarrier.init.shared.b64 [%0], 1;" :: "r"(mb1) : "memory");
    }
    __syncthreads();
    if (threadIdx.x == 0) {
        asm volatile("mbarrier.arrive.expect_tx.shared.b64 _, [%0], %1;"
                     :: "r"(mb0), "r"(bytesA) : "memory");
        asm volatile("cp.async.bulk.shared::cta.global.mbarrier::complete_tx::bytes"
                     " [%0], [%1], %2, [%3];"
                     :: "r"(smi_a), "l"(src), "r"(bytesA), "r"(mb0) : "memory");
        asm volatile("mbarrier.arrive.expect_tx.shared.b64 _, [%0], %1;"
                     :: "r"(mb1), "r"(bytesB) : "memory");
        asm volatile("cp.async.bulk.shared::cta.global.mbarrier::complete_tx::bytes"
                     " [%0], [%1], %2, [%3];"
                     :: "r"(smi_a + 5 * Wd * 4), "l"(src + 5 * Wd),
                        "r"(bytesB), "r"(mb1) : "memory");
    }

    float s = 0.5f * __ldg(t + (img & 127));
    float* op = out + (size_t)img * (OHd * OWd);
    int tid  = threadIdx.x;
    int w    = tid >> 5;                 // 0..1
    int lane = tid & 31;
    int j0   = 2 * lane;
    bool lastlane = (lane == 31);

    // phase 1: output row w (inputs 2w..2w+2 <= 4, chunk A only)
    mbar_wait(mb0, 0);
    do_row(smi, w, op, i0, lane, j0, lastlane, s);

    // phase 2: output row w+2 (inputs 4..8, chunk B)
    mbar_wait(mb1, 0);
    int i = w + 2;
    if (i < nout)
        do_row(smi, i, op, i0, lane, j0, lastlane, s);
}

extern "C" void kernel_launch(void* const* d_in, const int* in_sizes, int n_in,
                              void* d_out, int out_size) {
    const float* f = (const float*)d_in[0];   // [16,128,256,256] fp32
    const float* t = (const float*)d_in[1];   // [128] fp32
    float* out = (float*)d_out;               // [16,128,127,127] fp32
    // 2048 images * 32 tiles = 65536 blocks, 64 threads each
    parabolic_pool2d_kernel<<<65536, 64>>>(f, t, out);
}